// round 14
// baseline (speedup 1.0000x reference)
#include <cuda_runtime.h>
#include <cstdint>

// Round 14: fragment-native smem layout -> zero A-operand marshalling.
// SASS HMMA needs A in an aligned register quad; previous layout forced ~4
// MOVs per unique A-quad (= measured alu 40%). Fix: m16 rows pair across z
// (row r = (z,x=r), row r+8 = (z+2,x=r)); smem stores pre-interleaved quads
//   hp[k][h][hy][hx][g] = {z_h ch(4g+2k), z_{h+2} ch(4g+2k),
//                          z_h ch(4g+2k+1), z_{h+2} ch(4g+2k+1)}
// so each A-fragment is ONE LDS.128 straight into the MMA operand quad.
// Pairs (h,h+2), h=0..3 cover all taps with no y-duplication: 51.2KB smem.
// tile = 256 voxels (4z x 8y x 8x), 4 warps (warp = y-pair), 4 blocks/SM.

constexpr int N_TOTAL = 409600;
constexpr int W_FLOATS = 27 * 16 * 16;     // [tap][cout][ch]
constexpr int SMEM_BYTES = 2 * 400 * 16 * 4;   // 51200

__device__ float d_ws[W_FLOATS];

__device__ __forceinline__ float cvt_tf32(float v) {
    uint32_t o; asm("cvt.rna.tf32.f32 %0, %1;" : "=r"(o) : "f"(v));
    return __uint_as_float(o);
}

// A-fragment arrives as one uint4 (aligned quad), B as one uint2 (aligned pair).
__device__ __forceinline__ void mma_q(float c[4], uint4 q, uint2 b) {
    asm volatile("mma.sync.aligned.m16n8k8.row.col.f32.tf32.tf32.f32 "
                 "{%0,%1,%2,%3}, {%4,%5,%6,%7}, {%8,%9}, {%0,%1,%2,%3};"
                 : "+f"(c[0]), "+f"(c[1]), "+f"(c[2]), "+f"(c[3])
                 : "r"(q.x), "r"(q.y), "r"(q.z), "r"(q.w), "r"(b.x), "r"(b.y));
}

// ---- prep: transpose + rna-round weights once: d_ws[tap][cout][ch] ----
__global__ void weight_prep_kernel(const float* __restrict__ wgt) {
    int i = blockIdx.x * 256 + threadIdx.x;
    if (i >= W_FLOATS) return;
    int tap = i >> 8;
    int rem = i & 255;
    int cout = rem >> 4, ch = rem & 15;
    d_ws[tap * 256 + cout * 16 + ch] = cvt_tf32(wgt[(cout * 16 + ch) * 27 + tap]);
}

__global__ __launch_bounds__(128, 4)
void conv3d_mma_kernel(const float* __restrict__ in,
                       const float* __restrict__ bias, float* __restrict__ out)
{
    extern __shared__ __align__(16) uint32_t hp[];   // [k 2][item 400][quad 4]

    const int t = threadIdx.x;
    const int wid = t >> 5, lane = t & 31;
    const int r4 = lane >> 2, c4 = lane & 3;
    const int ybase = wid << 1;                      // warp's y-pair

    // ---- decode block -> (batch, level, tile). 256-voxel tiles. ----
    int bid = blockIdx.x;
    int b = bid / 1600;
    int tl = bid - b * 1600;
    int R, nbase, lt;
    if (tl < 16)       { R = 16; nbase = 0;      lt = tl;       }
    else if (tl < 144) { R = 32; nbase = 4096;   lt = tl - 16;  }
    else if (tl < 576) { R = 48; nbase = 36864;  lt = tl - 144; }
    else               { R = 64; nbase = 147456; lt = tl - 576; }
    const int td = R >> 3;
    const int tx = lt % td; const int t2 = lt / td;
    const int ty = t2 % td; const int tz = t2 / td;
    const int x0 = tx << 3, y0 = ty << 3, z0 = tz << 2;

    // ---- stage halo: z-pair-interleaved quads ----
    // item = (h, hy, hx), h=0..3; loads rows z0+h-1 and z0+h+1, writes 8 quads.
    const uint4* inq = (const uint4*)(in + ((size_t)b * N_TOTAL + nbase) * 16);
    for (int it = t; it < 400; it += 128) {
        int hx = it % 10; int r2 = it / 10; int hy = r2 % 10; int h = r2 / 10;
        int gx = x0 + hx - 1, gy = y0 + hy - 1;
        int gz1 = z0 + h - 1, gz2 = z0 + h + 1;
        bool okxy = ((unsigned)gx < (unsigned)R) && ((unsigned)gy < (unsigned)R);
        uint4 za[4], zb[4];
        #pragma unroll
        for (int g = 0; g < 4; ++g) {
            za[g] = make_uint4(0u, 0u, 0u, 0u);
            zb[g] = make_uint4(0u, 0u, 0u, 0u);
        }
        if (okxy && (unsigned)gz1 < (unsigned)R) {
            const uint4* p = inq + (size_t)((gz1 * R + gy) * R + gx) * 4;
            za[0] = p[0]; za[1] = p[1]; za[2] = p[2]; za[3] = p[3];
        }
        if (okxy && (unsigned)gz2 < (unsigned)R) {
            const uint4* p = inq + (size_t)((gz2 * R + gy) * R + gx) * 4;
            zb[0] = p[0]; zb[1] = p[1]; zb[2] = p[2]; zb[3] = p[3];
        }
        uint4* d0 = (uint4*)hp + it * 4;           // kstep 0
        uint4* d1 = (uint4*)hp + (400 + it) * 4;   // kstep 1
        #pragma unroll
        for (int g = 0; g < 4; ++g) {
            d0[g] = make_uint4(za[g].x, zb[g].x, za[g].y, zb[g].y);
            d1[g] = make_uint4(za[g].z, zb[g].z, za[g].w, zb[g].w);
        }
    }
    __syncthreads();

    // ---- compute: acc[zp][yy][n][4]; warp covers tiles (zp, ybase+yy) ----
    float acc[2][2][2][4];
    #pragma unroll
    for (int zp = 0; zp < 2; ++zp)
        #pragma unroll
        for (int yy = 0; yy < 2; ++yy)
            #pragma unroll
            for (int n = 0; n < 2; ++n)
                #pragma unroll
                for (int k = 0; k < 4; ++k) acc[zp][yy][n][k] = 0.f;

    const uint4* hpq = (const uint4*)hp;
    const uint2* wb  = (const uint2*)d_ws;   // pair (tap*128 + cout*8 + 2*c4 + k)
    const int wboff  = 2 * c4;

    #pragma unroll 1
    for (int dx = 0; dx < 3; ++dx) {
        #pragma unroll
        for (int dz = 0; dz < 3; ++dz) {
            #pragma unroll
            for (int k = 0; k < 2; ++k) {
                // window: 8 fragment quads, one LDS.128 each (conflict-free)
                uint4 qw[2][4];
                #pragma unroll
                for (int hh = 0; hh < 2; ++hh)
                    #pragma unroll
                    for (int r = 0; r < 4; ++r)
                        qw[hh][r] = hpq[(k * 400 + (dz + hh) * 100 +
                                         (ybase + r) * 10 + (r4 + dx)) * 4 + c4];
                #pragma unroll
                for (int dy = 0; dy < 3; ++dy) {
                    const int tap = (dz * 3 + dy) * 3 + dx;
                    uint2 bl = __ldg(wb + tap * 128 + r4 * 8 + wboff + k);
                    uint2 bh = __ldg(wb + tap * 128 + (r4 + 8) * 8 + wboff + k);
                    #pragma unroll
                    for (int zp = 0; zp < 2; ++zp)
                        #pragma unroll
                        for (int yy = 0; yy < 2; ++yy) {
                            mma_q(acc[zp][yy][0], qw[zp][yy + dy], bl);
                            mma_q(acc[zp][yy][1], qw[zp][yy + dy], bh);
                        }
                }
            }
        }
    }

    // ---- epilogue: +bias, store.  c0/c1 -> z0+zp, c2/c3 -> z0+zp+2 ----
    const int n0 = 2 * c4;
    const float bl0 = bias[n0],     bl1 = bias[n0 + 1];
    const float bh0 = bias[8 + n0], bh1 = bias[8 + n0 + 1];
    const int gx = x0 + r4;

    #pragma unroll
    for (int zp = 0; zp < 2; ++zp) {
        #pragma unroll
        for (int yy = 0; yy < 2; ++yy) {
            const int gy = y0 + ybase + yy;
            const int gz_lo = z0 + zp, gz_hi = z0 + zp + 2;
            float* olo = out + ((size_t)b * N_TOTAL + nbase +
                                (size_t)((gz_lo * R + gy) * R + gx)) * 16;
            float* ohi = out + ((size_t)b * N_TOTAL + nbase +
                                (size_t)((gz_hi * R + gy) * R + gx)) * 16;
            *(float2*)(olo + n0)     = make_float2(acc[zp][yy][0][0] + bl0,
                                                   acc[zp][yy][0][1] + bl1);
            *(float2*)(olo + 8 + n0) = make_float2(acc[zp][yy][1][0] + bh0,
                                                   acc[zp][yy][1][1] + bh1);
            *(float2*)(ohi + n0)     = make_float2(acc[zp][yy][0][2] + bl0,
                                                   acc[zp][yy][0][3] + bl1);
            *(float2*)(ohi + 8 + n0) = make_float2(acc[zp][yy][1][2] + bh0,
                                                   acc[zp][yy][1][3] + bh1);
        }
    }
}

extern "C" void kernel_launch(void* const* d_in, const int* in_sizes, int n_in,
                              void* d_out, int out_size) {
    (void)in_sizes; (void)n_in; (void)out_size;
    const float* in  = (const float*)d_in[0];
    const float* w   = (const float*)d_in[1];
    const float* bs  = (const float*)d_in[2];
    float* out = (float*)d_out;

    weight_prep_kernel<<<27, 256>>>(w);

    cudaFuncSetAttribute(conv3d_mma_kernel,
                         cudaFuncAttributeMaxDynamicSharedMemorySize, SMEM_BYTES);
    conv3d_mma_kernel<<<6400, 128, SMEM_BYTES>>>(in, bs, out);
}

// round 15
// speedup vs baseline: 1.2872x; 1.2872x over previous
#include <cuda_runtime.h>
#include <cstdint>

// Round 15: compose R14's marshalling-free fragments (alu 40%->7%, proven)
// with conflict-free staging and R13-level LDS volume.
//  - smem layout [g 4][k 2][item 400] uint4, g-plane stride 802 u4 (12832B,
//    = 32 mod 128): staging STS and compute LDS both bank-conflict-free.
//  - staging by (g = t&3, item): coalesced LDG.128, 2 STS.128 per slot.
//  - dz-sliding window: each h-plane loaded once per (dx,k): 96 LDS/warp.
// tile = 256 voxels (4z x 8y x 8x); m16 rows pair across z (r, r+8 = z, z+2).
// 4 warps (warp = y-pair), 4 blocks/SM.

constexpr int N_TOTAL = 409600;
constexpr int W_FLOATS = 27 * 16 * 16;          // [tap][cout][ch]
constexpr int PG = 802;                          // g-plane stride, uint4 units
constexpr int SMEM_BYTES = (3 * PG + 800) * 16;  // 51296

__device__ float d_ws[W_FLOATS];

__device__ __forceinline__ float cvt_tf32(float v) {
    uint32_t o; asm("cvt.rna.tf32.f32 %0, %1;" : "=r"(o) : "f"(v));
    return __uint_as_float(o);
}

__device__ __forceinline__ void mma_q(float c[4], uint4 q, uint2 b) {
    asm volatile("mma.sync.aligned.m16n8k8.row.col.f32.tf32.tf32.f32 "
                 "{%0,%1,%2,%3}, {%4,%5,%6,%7}, {%8,%9}, {%0,%1,%2,%3};"
                 : "+f"(c[0]), "+f"(c[1]), "+f"(c[2]), "+f"(c[3])
                 : "r"(q.x), "r"(q.y), "r"(q.z), "r"(q.w), "r"(b.x), "r"(b.y));
}

// ---- prep: transpose + rna-round weights once: d_ws[tap][cout][ch] ----
__global__ void weight_prep_kernel(const float* __restrict__ wgt) {
    int i = blockIdx.x * 256 + threadIdx.x;
    if (i >= W_FLOATS) return;
    int tap = i >> 8;
    int rem = i & 255;
    int cout = rem >> 4, ch = rem & 15;
    d_ws[tap * 256 + cout * 16 + ch] = cvt_tf32(wgt[(cout * 16 + ch) * 27 + tap]);
}

// one dz stage: planes plo (h=dz, feeds acc[0]) and phi (h=dz+1, feeds acc[1])
__device__ __forceinline__ void dz_stage(float acc[2][2][2][4],
                                         const uint4 plo[4], const uint4 phi[4],
                                         const uint2* __restrict__ wb,
                                         int dz, int dx, int k, int r4, int c4) {
    #pragma unroll
    for (int dy = 0; dy < 3; ++dy) {
        const int tap = (dz * 3 + dy) * 3 + dx;
        uint2 bl = __ldg(wb + tap * 128 + r4 * 8 + 2 * c4 + k);
        uint2 bh = __ldg(wb + tap * 128 + (r4 + 8) * 8 + 2 * c4 + k);
        #pragma unroll
        for (int yy = 0; yy < 2; ++yy) {
            mma_q(acc[0][yy][0], plo[yy + dy], bl);
            mma_q(acc[0][yy][1], plo[yy + dy], bh);
            mma_q(acc[1][yy][0], phi[yy + dy], bl);
            mma_q(acc[1][yy][1], phi[yy + dy], bh);
        }
    }
}

__global__ __launch_bounds__(128, 4)
void conv3d_mma_kernel(const float* __restrict__ in,
                       const float* __restrict__ bias, float* __restrict__ out)
{
    extern __shared__ __align__(16) uint4 hp[];   // [g][k][item], stride PG

    const int t = threadIdx.x;
    const int wid = t >> 5, lane = t & 31;
    const int r4 = lane >> 2, c4 = lane & 3;
    const int ybase = wid << 1;

    // ---- decode block -> (batch, level, tile). 256-voxel tiles. ----
    int bid = blockIdx.x;
    int b = bid / 1600;
    int tl = bid - b * 1600;
    int R, nbase, lt;
    if (tl < 16)       { R = 16; nbase = 0;      lt = tl;       }
    else if (tl < 144) { R = 32; nbase = 4096;   lt = tl - 16;  }
    else if (tl < 576) { R = 48; nbase = 36864;  lt = tl - 144; }
    else               { R = 64; nbase = 147456; lt = tl - 576; }
    const int td = R >> 3;
    const int tx = lt % td; const int t2 = lt / td;
    const int ty = t2 % td; const int tz = t2 / td;
    const int x0 = tx << 3, y0 = ty << 3, z0 = tz << 2;

    // ---- stage halo: thread = (g = t&3, item stream), 13 passes ----
    // item = h*100 + hy*10 + hx, h = 0..3 pairs rows (z0+h-1, z0+h+1).
    const uint4* inq = (const uint4*)(in + ((size_t)b * N_TOTAL + nbase) * 16);
    {
        const int g = t & 3;
        int it = t >> 2;                       // 0..31
        int hx = it % 10, hy = it / 10, h = 0; // it<=31 -> hy<=3, h=0
        #pragma unroll
        for (int pass = 0; pass < 13; ++pass) {
            if (it < 400) {
                int gx = x0 + hx - 1, gy = y0 + hy - 1;
                int gz1 = z0 + h - 1, gz2 = z0 + h + 1;
                bool okxy = ((unsigned)gx < (unsigned)R) &&
                            ((unsigned)gy < (unsigned)R);
                uint4 za = make_uint4(0u, 0u, 0u, 0u);
                uint4 zb = make_uint4(0u, 0u, 0u, 0u);
                if (okxy && (unsigned)gz1 < (unsigned)R)
                    za = inq[(size_t)((gz1 * R + gy) * R + gx) * 4 + g];
                if (okxy && (unsigned)gz2 < (unsigned)R)
                    zb = inq[(size_t)((gz2 * R + gy) * R + gx) * 4 + g];
                hp[g * PG + it]       = make_uint4(za.x, zb.x, za.y, zb.y);
                hp[g * PG + 400 + it] = make_uint4(za.z, zb.z, za.w, zb.w);
            }
            // advance 32 items: 32 = 3*10 + 2
            hx += 2; hy += 3;
            if (hx >= 10) { hx -= 10; hy += 1; }
            if (hy >= 10) { hy -= 10; h += 1; }
            it += 32;
        }
    }
    __syncthreads();

    // ---- compute: acc[zp][yy][n][4]; dz-sliding plane window ----
    float acc[2][2][2][4];
    #pragma unroll
    for (int zp = 0; zp < 2; ++zp)
        #pragma unroll
        for (int yy = 0; yy < 2; ++yy)
            #pragma unroll
            for (int n = 0; n < 2; ++n)
                #pragma unroll
                for (int q = 0; q < 4; ++q) acc[zp][yy][n][q] = 0.f;

    const uint2* wb = (const uint2*)d_ws;

    #pragma unroll 1
    for (int dx = 0; dx < 3; ++dx) {
        #pragma unroll
        for (int k = 0; k < 2; ++k) {
            // base of this thread's fragment column (item h=0, r=0)
            const uint4* pb = hp + (size_t)c4 * PG + k * 400 +
                              ybase * 10 + r4 + dx;
            uint4 pA[4], pB[4];
            #pragma unroll
            for (int r = 0; r < 4; ++r) pA[r] = pb[r * 10];           // h=0
            #pragma unroll
            for (int r = 0; r < 4; ++r) pB[r] = pb[100 + r * 10];     // h=1
            dz_stage(acc, pA, pB, wb, 0, dx, k, r4, c4);
            #pragma unroll
            for (int r = 0; r < 4; ++r) pA[r] = pb[200 + r * 10];     // h=2
            dz_stage(acc, pB, pA, wb, 1, dx, k, r4, c4);
            #pragma unroll
            for (int r = 0; r < 4; ++r) pB[r] = pb[300 + r * 10];     // h=3
            dz_stage(acc, pA, pB, wb, 2, dx, k, r4, c4);
        }
    }

    // ---- epilogue: +bias, store.  c0/c1 -> z0+zp, c2/c3 -> z0+zp+2 ----
    const int n0 = 2 * c4;
    const float bl0 = bias[n0],     bl1 = bias[n0 + 1];
    const float bh0 = bias[8 + n0], bh1 = bias[8 + n0 + 1];
    const int gx = x0 + r4;

    #pragma unroll
    for (int zp = 0; zp < 2; ++zp) {
        #pragma unroll
        for (int yy = 0; yy < 2; ++yy) {
            const int gy = y0 + ybase + yy;
            const int gz_lo = z0 + zp, gz_hi = z0 + zp + 2;
            float* olo = out + ((size_t)b * N_TOTAL + nbase +
                                (size_t)((gz_lo * R + gy) * R + gx)) * 16;
            float* ohi = out + ((size_t)b * N_TOTAL + nbase +
                                (size_t)((gz_hi * R + gy) * R + gx)) * 16;
            *(float2*)(olo + n0)     = make_float2(acc[zp][yy][0][0] + bl0,
                                                   acc[zp][yy][0][1] + bl1);
            *(float2*)(olo + 8 + n0) = make_float2(acc[zp][yy][1][0] + bh0,
                                                   acc[zp][yy][1][1] + bh1);
            *(float2*)(ohi + n0)     = make_float2(acc[zp][yy][0][2] + bl0,
                                                   acc[zp][yy][0][3] + bl1);
            *(float2*)(ohi + 8 + n0) = make_float2(acc[zp][yy][1][2] + bh0,
                                                   acc[zp][yy][1][3] + bh1);
        }
    }
}

extern "C" void kernel_launch(void* const* d_in, const int* in_sizes, int n_in,
                              void* d_out, int out_size) {
    (void)in_sizes; (void)n_in; (void)out_size;
    const float* in  = (const float*)d_in[0];
    const float* w   = (const float*)d_in[1];
    const float* bs  = (const float*)d_in[2];
    float* out = (float*)d_out;

    weight_prep_kernel<<<27, 256>>>(w);

    cudaFuncSetAttribute(conv3d_mma_kernel,
                         cudaFuncAttributeMaxDynamicSharedMemorySize, SMEM_BYTES);
    conv3d_mma_kernel<<<6400, 128, SMEM_BYTES>>>(in, bs, out);
}

// round 16
// speedup vs baseline: 1.4139x; 1.0984x over previous
#include <cuda_runtime.h>
#include <cstdint>

// Round 16: R15 + B repacked for 2-wavefront warp loads.
// R15 audit: B loads (uint2 at 16B lane stride) cost 4 wf each with half the
// line wasted -> 1728 wf/block, the largest single L1 term. New weight layout
//   d_ws[tap][k][half][r4][c4][2 floats]
// makes each B fragment load 32 lanes x 8B CONTIGUOUS (256B = 2 wf); bh is
// bl + 32 uint2. B traffic halves (864 wf/block). No other changes: A layout,
// staging, dz-sliding window, marshalling-free MMA quads all as in R15.
// tile = 256 voxels (4z x 8y x 8x); m16 rows pair across z; 4 warps; 4 blk/SM.

constexpr int N_TOTAL = 409600;
constexpr int W_FLOATS = 27 * 16 * 16;          // repacked, see prep kernel
constexpr int PG = 802;                          // g-plane stride, uint4 units
constexpr int SMEM_BYTES = (3 * PG + 800) * 16;  // 51296

__device__ float d_ws[W_FLOATS];

__device__ __forceinline__ float cvt_tf32(float v) {
    uint32_t o; asm("cvt.rna.tf32.f32 %0, %1;" : "=r"(o) : "f"(v));
    return __uint_as_float(o);
}

__device__ __forceinline__ void mma_q(float c[4], uint4 q, uint2 b) {
    asm volatile("mma.sync.aligned.m16n8k8.row.col.f32.tf32.tf32.f32 "
                 "{%0,%1,%2,%3}, {%4,%5,%6,%7}, {%8,%9}, {%0,%1,%2,%3};"
                 : "+f"(c[0]), "+f"(c[1]), "+f"(c[2]), "+f"(c[3])
                 : "r"(q.x), "r"(q.y), "r"(q.z), "r"(q.w), "r"(b.x), "r"(b.y));
}

// ---- prep: rna-round + repack weights once ----
// float index i = tap*256 + k*128 + h*64 + r4*8 + c4*2 + j
//   -> ws value for cout = 8h + r4, ch = 4*c4 + 2*k + j.
// A warp's fragment load for (tap, k, h) is then 256B contiguous.
__global__ void weight_prep_kernel(const float* __restrict__ wgt) {
    int i = blockIdx.x * 256 + threadIdx.x;
    if (i >= W_FLOATS) return;
    int j   = i & 1;
    int c4  = (i >> 1) & 3;
    int r4  = (i >> 3) & 7;
    int h   = (i >> 6) & 1;
    int k   = (i >> 7) & 1;
    int tap = i >> 8;
    int ch   = 4 * c4 + 2 * k + j;
    int cout = 8 * h + r4;
    d_ws[i] = cvt_tf32(wgt[(cout * 16 + ch) * 27 + tap]);
}

// one dz stage: planes plo (feeds acc[0]) and phi (feeds acc[1]).
// wbk = (uint2*)d_ws + k*64 + r4*4 + c4 (precomputed); bl = wbk + tap*128.
__device__ __forceinline__ void dz_stage(float acc[2][2][2][4],
                                         const uint4 plo[4], const uint4 phi[4],
                                         const uint2* __restrict__ wbk,
                                         int dz, int dx) {
    #pragma unroll
    for (int dy = 0; dy < 3; ++dy) {
        const int tap = (dz * 3 + dy) * 3 + dx;
        uint2 bl = __ldg(wbk + tap * 128);        // couts r4   (h=0)
        uint2 bh = __ldg(wbk + tap * 128 + 32);   // couts r4+8 (h=1)
        #pragma unroll
        for (int yy = 0; yy < 2; ++yy) {
            mma_q(acc[0][yy][0], plo[yy + dy], bl);
            mma_q(acc[0][yy][1], plo[yy + dy], bh);
            mma_q(acc[1][yy][0], phi[yy + dy], bl);
            mma_q(acc[1][yy][1], phi[yy + dy], bh);
        }
    }
}

__global__ __launch_bounds__(128, 4)
void conv3d_mma_kernel(const float* __restrict__ in,
                       const float* __restrict__ bias, float* __restrict__ out)
{
    extern __shared__ __align__(16) uint4 hp[];   // [g][k][item], stride PG

    const int t = threadIdx.x;
    const int wid = t >> 5, lane = t & 31;
    const int r4 = lane >> 2, c4 = lane & 3;
    const int ybase = wid << 1;

    // ---- decode block -> (batch, level, tile). 256-voxel tiles. ----
    int bid = blockIdx.x;
    int b = bid / 1600;
    int tl = bid - b * 1600;
    int R, nbase, lt;
    if (tl < 16)       { R = 16; nbase = 0;      lt = tl;       }
    else if (tl < 144) { R = 32; nbase = 4096;   lt = tl - 16;  }
    else if (tl < 576) { R = 48; nbase = 36864;  lt = tl - 144; }
    else               { R = 64; nbase = 147456; lt = tl - 576; }
    const int td = R >> 3;
    const int tx = lt % td; const int t2 = lt / td;
    const int ty = t2 % td; const int tz = t2 / td;
    const int x0 = tx << 3, y0 = ty << 3, z0 = tz << 2;

    // ---- stage halo: thread = (g = t&3, item stream), 13 passes ----
    const uint4* inq = (const uint4*)(in + ((size_t)b * N_TOTAL + nbase) * 16);
    {
        const int g = t & 3;
        int it = t >> 2;
        int hx = it % 10, hy = it / 10, h = 0;
        #pragma unroll
        for (int pass = 0; pass < 13; ++pass) {
            if (it < 400) {
                int gx = x0 + hx - 1, gy = y0 + hy - 1;
                int gz1 = z0 + h - 1, gz2 = z0 + h + 1;
                bool okxy = ((unsigned)gx < (unsigned)R) &&
                            ((unsigned)gy < (unsigned)R);
                uint4 za = make_uint4(0u, 0u, 0u, 0u);
                uint4 zb = make_uint4(0u, 0u, 0u, 0u);
                if (okxy && (unsigned)gz1 < (unsigned)R)
                    za = inq[(size_t)((gz1 * R + gy) * R + gx) * 4 + g];
                if (okxy && (unsigned)gz2 < (unsigned)R)
                    zb = inq[(size_t)((gz2 * R + gy) * R + gx) * 4 + g];
                hp[g * PG + it]       = make_uint4(za.x, zb.x, za.y, zb.y);
                hp[g * PG + 400 + it] = make_uint4(za.z, zb.z, za.w, zb.w);
            }
            hx += 2; hy += 3;
            if (hx >= 10) { hx -= 10; hy += 1; }
            if (hy >= 10) { hy -= 10; h += 1; }
            it += 32;
        }
    }
    __syncthreads();

    // ---- compute: acc[zp][yy][n][4]; dz-sliding plane window ----
    float acc[2][2][2][4];
    #pragma unroll
    for (int zp = 0; zp < 2; ++zp)
        #pragma unroll
        for (int yy = 0; yy < 2; ++yy)
            #pragma unroll
            for (int n = 0; n < 2; ++n)
                #pragma unroll
                for (int q = 0; q < 4; ++q) acc[zp][yy][n][q] = 0.f;

    #pragma unroll 1
    for (int dx = 0; dx < 3; ++dx) {
        #pragma unroll
        for (int k = 0; k < 2; ++k) {
            const uint2* wbk = (const uint2*)d_ws + k * 64 + r4 * 4 + c4;
            const uint4* pb = hp + (size_t)c4 * PG + k * 400 +
                              ybase * 10 + r4 + dx;
            uint4 pA[4], pB[4];
            #pragma unroll
            for (int r = 0; r < 4; ++r) pA[r] = pb[r * 10];           // h=0
            #pragma unroll
            for (int r = 0; r < 4; ++r) pB[r] = pb[100 + r * 10];     // h=1
            dz_stage(acc, pA, pB, wbk, 0, dx);
            #pragma unroll
            for (int r = 0; r < 4; ++r) pA[r] = pb[200 + r * 10];     // h=2
            dz_stage(acc, pB, pA, wbk, 1, dx);
            #pragma unroll
            for (int r = 0; r < 4; ++r) pB[r] = pb[300 + r * 10];     // h=3
            dz_stage(acc, pA, pB, wbk, 2, dx);
        }
    }

    // ---- epilogue: +bias, store.  c0/c1 -> z0+zp, c2/c3 -> z0+zp+2 ----
    const int n0 = 2 * c4;
    const float bl0 = bias[n0],     bl1 = bias[n0 + 1];
    const float bh0 = bias[8 + n0], bh1 = bias[8 + n0 + 1];
    const int gx = x0 + r4;

    #pragma unroll
    for (int zp = 0; zp < 2; ++zp) {
        #pragma unroll
        for (int yy = 0; yy < 2; ++yy) {
            const int gy = y0 + ybase + yy;
            const int gz_lo = z0 + zp, gz_hi = z0 + zp + 2;
            float* olo = out + ((size_t)b * N_TOTAL + nbase +
                                (size_t)((gz_lo * R + gy) * R + gx)) * 16;
            float* ohi = out + ((size_t)b * N_TOTAL + nbase +
                                (size_t)((gz_hi * R + gy) * R + gx)) * 16;
            *(float2*)(olo + n0)     = make_float2(acc[zp][yy][0][0] + bl0,
                                                   acc[zp][yy][0][1] + bl1);
            *(float2*)(olo + 8 + n0) = make_float2(acc[zp][yy][1][0] + bh0,
                                                   acc[zp][yy][1][1] + bh1);
            *(float2*)(ohi + n0)     = make_float2(acc[zp][yy][0][2] + bl0,
                                                   acc[zp][yy][0][3] + bl1);
            *(float2*)(ohi + 8 + n0) = make_float2(acc[zp][yy][1][2] + bh0,
                                                   acc[zp][yy][1][3] + bh1);
        }
    }
}

extern "C" void kernel_launch(void* const* d_in, const int* in_sizes, int n_in,
                              void* d_out, int out_size) {
    (void)in_sizes; (void)n_in; (void)out_size;
    const float* in  = (const float*)d_in[0];
    const float* w   = (const float*)d_in[1];
    const float* bs  = (const float*)d_in[2];
    float* out = (float*)d_out;

    weight_prep_kernel<<<27, 256>>>(w);

    cudaFuncSetAttribute(conv3d_mma_kernel,
                         cudaFuncAttributeMaxDynamicSharedMemorySize, SMEM_BYTES);
    conv3d_mma_kernel<<<6400, 128, SMEM_BYTES>>>(in, bs, out);
}

// round 17
// speedup vs baseline: 1.5437x; 1.0918x over previous
#include <cuda_runtime.h>
#include <cstdint>

// Round 17: 8x8x8 tile (512 voxels) with z-quad m16 pairing (z, z+4).
// Halo pairs h=0..5 store rows (z0+h-1, z0+h+3): 12 z-rows, 76.9KB smem.
// Per (dx,k): sliding 4-pair window, 24 A-loads feed 144 MMAs (ratio 6.0
// vs 4.5) -> per-voxel L1 wavefronts drop 11.8 -> ~7.9; tensor becomes the
// binding pipe. Warp = y-pair; acc = 4 zt x 2 yy x 2 n. 3 blocks/SM.
// B layout as R16 (2-wavefront contiguous fragment loads). Weights rna->tf32;
// activations raw fp32 (HW tf32 truncation).

constexpr int N_TOTAL = 409600;
constexpr int W_FLOATS = 27 * 16 * 16;
constexpr int PG = 1202;                          // g-plane stride (uint4); %8==2
constexpr int SMEM_BYTES = (3 * PG + 1200) * 16;  // 76896

__device__ float d_ws[W_FLOATS];

__device__ __forceinline__ float cvt_tf32(float v) {
    uint32_t o; asm("cvt.rna.tf32.f32 %0, %1;" : "=r"(o) : "f"(v));
    return __uint_as_float(o);
}

__device__ __forceinline__ void mma_q(float c[4], uint4 q, uint2 b) {
    asm volatile("mma.sync.aligned.m16n8k8.row.col.f32.tf32.tf32.f32 "
                 "{%0,%1,%2,%3}, {%4,%5,%6,%7}, {%8,%9}, {%0,%1,%2,%3};"
                 : "+f"(c[0]), "+f"(c[1]), "+f"(c[2]), "+f"(c[3])
                 : "r"(q.x), "r"(q.y), "r"(q.z), "r"(q.w), "r"(b.x), "r"(b.y));
}

// ---- prep: rna-round + repack weights (same layout as R16) ----
// i = tap*256 + k*128 + h*64 + r4*8 + c4*2 + j -> cout = 8h+r4, ch = 4c4+2k+j
__global__ void weight_prep_kernel(const float* __restrict__ wgt) {
    int i = blockIdx.x * 256 + threadIdx.x;
    if (i >= W_FLOATS) return;
    int j   = i & 1;
    int c4  = (i >> 1) & 3;
    int r4  = (i >> 3) & 7;
    int h   = (i >> 6) & 1;
    int k   = (i >> 7) & 1;
    int tap = i >> 8;
    d_ws[i] = cvt_tf32(wgt[((8 * h + r4) * 16 + 4 * c4 + 2 * k + j) * 27 + tap]);
}

// One dz stage. P0..P3 are the 4-row windows for ztile 0..3 (already in
// ring order: P_zt = pair h = zt + dz).
__device__ __forceinline__ void dz_stage(float acc[4][2][2][4],
                                         const uint4 P0[4], const uint4 P1[4],
                                         const uint4 P2[4], const uint4 P3[4],
                                         const uint2* __restrict__ wbk,
                                         int dz, int dx) {
    #pragma unroll
    for (int dy = 0; dy < 3; ++dy) {
        const int tap = (dz * 3 + dy) * 3 + dx;
        uint2 bl = __ldg(wbk + tap * 128);        // couts r4   (h=0)
        uint2 bh = __ldg(wbk + tap * 128 + 32);   // couts r4+8 (h=1)
        #pragma unroll
        for (int yy = 0; yy < 2; ++yy) {
            mma_q(acc[0][yy][0], P0[yy + dy], bl);
            mma_q(acc[0][yy][1], P0[yy + dy], bh);
            mma_q(acc[1][yy][0], P1[yy + dy], bl);
            mma_q(acc[1][yy][1], P1[yy + dy], bh);
            mma_q(acc[2][yy][0], P2[yy + dy], bl);
            mma_q(acc[2][yy][1], P2[yy + dy], bh);
            mma_q(acc[3][yy][0], P3[yy + dy], bl);
            mma_q(acc[3][yy][1], P3[yy + dy], bh);
        }
    }
}

__global__ __launch_bounds__(128, 3)
void conv3d_mma_kernel(const float* __restrict__ in,
                       const float* __restrict__ bias, float* __restrict__ out)
{
    extern __shared__ __align__(16) uint4 hp[];   // [g 4][k 2][item 600], stride PG

    const int t = threadIdx.x;
    const int wid = t >> 5, lane = t & 31;
    const int r4 = lane >> 2, c4 = lane & 3;
    const int ybase = wid << 1;

    // ---- decode block -> (batch, level, tile). 512-voxel tiles. ----
    // tiles/batch: R16:8, R32:64, R48:216, R64:512 -> 800; grid = 3200.
    int bid = blockIdx.x;
    int b = bid / 800;
    int tl = bid - b * 800;
    int R, nbase, lt;
    if (tl < 8)        { R = 16; nbase = 0;      lt = tl;       }
    else if (tl < 72)  { R = 32; nbase = 4096;   lt = tl - 8;   }
    else if (tl < 288) { R = 48; nbase = 36864;  lt = tl - 72;  }
    else               { R = 64; nbase = 147456; lt = tl - 288; }
    const int td = R >> 3;
    const int tx = lt % td; const int t2 = lt / td;
    const int ty = t2 % td; const int tz = t2 / td;
    const int x0 = tx << 3, y0 = ty << 3, z0 = tz << 3;

    // ---- stage halo: item = h*100 + hy*10 + hx, h = 0..5 pairs rows
    //      (z0+h-1, z0+h+3). thread = (g = t&3, item stream), 19 passes. ----
    const uint4* inq = (const uint4*)(in + ((size_t)b * N_TOTAL + nbase) * 16);
    {
        const int g = t & 3;
        int it = t >> 2;                       // 0..31
        int hx = it % 10, hy = it / 10, h = 0;
        #pragma unroll
        for (int pass = 0; pass < 19; ++pass) {
            if (it < 600) {
                int gx = x0 + hx - 1, gy = y0 + hy - 1;
                int gz1 = z0 + h - 1, gz2 = z0 + h + 3;
                bool okxy = ((unsigned)gx < (unsigned)R) &&
                            ((unsigned)gy < (unsigned)R);
                uint4 za = make_uint4(0u, 0u, 0u, 0u);
                uint4 zb = make_uint4(0u, 0u, 0u, 0u);
                if (okxy && (unsigned)gz1 < (unsigned)R)
                    za = inq[(size_t)((gz1 * R + gy) * R + gx) * 4 + g];
                if (okxy && (unsigned)gz2 < (unsigned)R)
                    zb = inq[(size_t)((gz2 * R + gy) * R + gx) * 4 + g];
                hp[g * PG + it]       = make_uint4(za.x, zb.x, za.y, zb.y);
                hp[g * PG + 600 + it] = make_uint4(za.z, zb.z, za.w, zb.w);
            }
            // advance 32 items: 32 = 3*10 + 2
            hx += 2; hy += 3;
            if (hx >= 10) { hx -= 10; hy += 1; }
            if (hy >= 10) { hy -= 10; h += 1; }
            it += 32;
        }
    }
    __syncthreads();

    // ---- compute: acc[zt][yy][n][4]; dz-sliding 4-pair window ----
    float acc[4][2][2][4];
    #pragma unroll
    for (int zt = 0; zt < 4; ++zt)
        #pragma unroll
        for (int yy = 0; yy < 2; ++yy)
            #pragma unroll
            for (int n = 0; n < 2; ++n)
                #pragma unroll
                for (int q = 0; q < 4; ++q) acc[zt][yy][n][q] = 0.f;

    #pragma unroll 1
    for (int dx = 0; dx < 3; ++dx) {
        #pragma unroll
        for (int k = 0; k < 2; ++k) {
            const uint2* wbk = (const uint2*)d_ws + k * 64 + r4 * 4 + c4;
            const uint4* pb = hp + (size_t)c4 * PG + k * 600 +
                              ybase * 10 + r4 + dx;
            uint4 W[4][4];   // ring of pairs; W[p][r] = pair h, window row r
            #pragma unroll
            for (int p = 0; p < 4; ++p)
                #pragma unroll
                for (int r = 0; r < 4; ++r)
                    W[p][r] = pb[p * 100 + r * 10];

            // stage dz=0: ztile zt uses pair zt
            dz_stage(acc, W[0], W[1], W[2], W[3], wbk, 0, dx);
            #pragma unroll
            for (int r = 0; r < 4; ++r) W[0][r] = pb[400 + r * 10];   // h=4
            // stage dz=1: pairs 1,2,3,4
            dz_stage(acc, W[1], W[2], W[3], W[0], wbk, 1, dx);
            #pragma unroll
            for (int r = 0; r < 4; ++r) W[1][r] = pb[500 + r * 10];   // h=5
            // stage dz=2: pairs 2,3,4,5
            dz_stage(acc, W[2], W[3], W[0], W[1], wbk, 2, dx);
        }
    }

    // ---- epilogue: +bias, store. c0/c1 -> z0+zt, c2/c3 -> z0+zt+4 ----
    const int n0 = 2 * c4;
    const float bl0 = bias[n0],     bl1 = bias[n0 + 1];
    const float bh0 = bias[8 + n0], bh1 = bias[8 + n0 + 1];
    const int gx = x0 + r4;

    #pragma unroll
    for (int zt = 0; zt < 4; ++zt) {
        #pragma unroll
        for (int yy = 0; yy < 2; ++yy) {
            const int gy = y0 + ybase + yy;
            const int gz_lo = z0 + zt, gz_hi = z0 + zt + 4;
            float* olo = out + ((size_t)b * N_TOTAL + nbase +
                                (size_t)((gz_lo * R + gy) * R + gx)) * 16;
            float* ohi = out + ((size_t)b * N_TOTAL + nbase +
                                (size_t)((gz_hi * R + gy) * R + gx)) * 16;
            *(float2*)(olo + n0)     = make_float2(acc[zt][yy][0][0] + bl0,
                                                   acc[zt][yy][0][1] + bl1);
            *(float2*)(olo + 8 + n0) = make_float2(acc[zt][yy][1][0] + bh0,
                                                   acc[zt][yy][1][1] + bh1);
            *(float2*)(ohi + n0)     = make_float2(acc[zt][yy][0][2] + bl0,
                                                   acc[zt][yy][0][3] + bl1);
            *(float2*)(ohi + 8 + n0) = make_float2(acc[zt][yy][1][2] + bh0,
                                                   acc[zt][yy][1][3] + bh1);
        }
    }
}

extern "C" void kernel_launch(void* const* d_in, const int* in_sizes, int n_in,
                              void* d_out, int out_size) {
    (void)in_sizes; (void)n_in; (void)out_size;
    const float* in  = (const float*)d_in[0];
    const float* w   = (const float*)d_in[1];
    const float* bs  = (const float*)d_in[2];
    float* out = (float*)d_out;

    weight_prep_kernel<<<27, 256>>>(w);

    cudaFuncSetAttribute(conv3d_mma_kernel,
                         cudaFuncAttributeMaxDynamicSharedMemorySize, SMEM_BYTES);
    conv3d_mma_kernel<<<3200, 128, SMEM_BYTES>>>(in, bs, out);
}